// round 8
// baseline (speedup 1.0000x reference)
#include <cuda_runtime.h>
#include <cstdint>
#include <cmath>

// ---------------------------------------------------------------------------
// Head_55671366091048 (sm_103a):
//   xc/yc/Wc = rna(x/y/W)  (tf32-valued f32 copies)
//   q = xc Wqc^T ; k = yc Wkc^T ; vT = (yc Wvc^T)^T    (one fused launch)
//   a = mask(q k^T) * d^-1/2    (strict lower; 128x256 blocks, skip 2bn>bm)
//   out = a vT^T                (per-128-row K limit)
//
// Single tcgen05 kind::tf32 GEMM template: 128x256 CTA tiles, TMEM 256 cols,
// 2-stage cp.async pipeline, 2 CTAs/SM (the round-6 lesson: 1 CTA/SM leaves
// every fence/sync/mbar latency exposed; cross-CTA overlap hides it).
// compute_103 PTX pass gets a naive fallback (never runs on HW).
// ---------------------------------------------------------------------------

#if defined(__CUDA_ARCH__) && defined(__CUDA_ARCH_FEAT_SM103_ALL)
#define USE_TCGEN05 1
#else
#define USE_TCGEN05 0
#endif

namespace {
constexpr int kNX = 8192;
constexpr int kNY = 8192;
constexpr int kC  = 2048;
constexpr int kD  = 512;

constexpr int BMC = 128;                 // CTA rows
constexpr int BNC = 256;                 // CTA cols
constexpr int KT  = 32;                  // K per smem tile (128B rows)
constexpr int SS  = 2;                   // pipeline stages
constexpr int ABYTES = BMC * 128;        // 16 KB
constexpr int BBYTES = BNC * 128;        // 32 KB
constexpr int STB = ABYTES + BBYTES;     // 48 KB
constexpr int MBAR_OFF = 64;
constexpr int DATA_OFF = 1024;
constexpr int SMEM_SZ = DATA_OFF + SS * STB;   // 99328 B -> 2 CTAs/SM

constexpr uint64_t DESC_BASE =
    (uint64_t(2) << 61) | (uint64_t(1) << 46) | (uint64_t(64) << 32) |
    (uint64_t(1) << 16);

// idesc kind::tf32: dtype F32, a/b TF32, N=256, M=128
constexpr uint32_t IDESC =
    (1u << 4) | (2u << 7) | (2u << 10) | ((BNC / 8) << 17) | (8u << 24);
}  // namespace

__device__ float g_xc[(size_t)kNX * kC];
__device__ float g_yc[(size_t)kNY * kC];
__device__ float g_wqc[(size_t)kD * kC];
__device__ float g_wkc[(size_t)kD * kC];
__device__ float g_wvc[(size_t)kD * kC];
__device__ float g_q[(size_t)kNX * kD];
__device__ float g_k[(size_t)kNY * kD];
__device__ float g_vT[(size_t)kD * kNY];
__device__ float g_a[(size_t)kNX * kNY];

// ---------------------------------------------------------------------------
__device__ __forceinline__ uint32_t smem_u32(const void* p) {
  uint32_t a;
  asm("{ .reg .u64 t; cvta.to.shared.u64 t, %1; cvt.u32.u64 %0, t; }"
      : "=r"(a) : "l"(p));
  return a;
}
__device__ __forceinline__ float tf32r(float f) {
  uint32_t u;
  asm("cvt.rna.tf32.f32 %0, %1;" : "=r"(u) : "f"(f));
  return __uint_as_float(u);
}
__device__ __forceinline__ float4 tf32r4(float4 v) {
  return make_float4(tf32r(v.x), tf32r(v.y), tf32r(v.z), tf32r(v.w));
}

// z in [0,NP): convert plane z
__global__ void cvt_kernel(const float* s0, float* d0, const float* s1,
                           float* d1, const float* s2, float* d2, int n) {
  const int z = blockIdx.z;
  const float* s = (z == 0) ? s0 : (z == 1) ? s1 : s2;
  float* d = (z == 0) ? d0 : (z == 1) ? d1 : d2;
  int i = (blockIdx.x * blockDim.x + threadIdx.x) * 4;
  const int stride = gridDim.x * blockDim.x * 4;
  for (; i < n; i += stride) *(float4*)(d + i) = tf32r4(*(const float4*)(s + i));
}

#if USE_TCGEN05
__device__ __forceinline__ void mbar_init(uint32_t addr, uint32_t cnt) {
  asm volatile("mbarrier.init.shared.b64 [%0], %1;" :: "r"(addr), "r"(cnt)
               : "memory");
}
__device__ __forceinline__ void mbar_inval(uint32_t addr) {
  asm volatile("mbarrier.inval.shared.b64 [%0];" :: "r"(addr) : "memory");
}
__device__ __forceinline__ void mbar_wait(uint32_t addr, uint32_t parity) {
  uint32_t done;
  asm volatile(
      "{\n\t.reg .pred p;\n\t"
      "mbarrier.try_wait.parity.acquire.cta.shared::cta.b64 p, [%1], %2;\n\t"
      "selp.b32 %0, 1, 0, p;\n\t}"
      : "=r"(done) : "r"(addr), "r"(parity) : "memory");
  if (!done) {
    asm volatile(
        "{\n\t.reg .pred P1;\n\t"
        "WL_%=:\n\t"
        "mbarrier.try_wait.parity.acquire.cta.shared::cta.b64 P1, [%0], %1, 0x989680;\n\t"
        "@P1 bra.uni WD_%=;\n\t"
        "bra.uni WL_%=;\n\t"
        "WD_%=:\n\t}"
        :: "r"(addr), "r"(parity) : "memory");
  }
}
__device__ __forceinline__ void tmem_alloc(uint32_t smem_dst, uint32_t ncols) {
  asm volatile(
      "tcgen05.alloc.cta_group::1.sync.aligned.shared::cta.b32 [%0], %1;"
      :: "r"(smem_dst), "r"(ncols) : "memory");
}
__device__ __forceinline__ void tmem_relinq() {
  asm volatile("tcgen05.relinquish_alloc_permit.cta_group::1.sync.aligned;");
}
__device__ __forceinline__ void tmem_dealloc(uint32_t tmem, uint32_t ncols) {
  asm volatile("tcgen05.dealloc.cta_group::1.sync.aligned.b32 %0, %1;"
               :: "r"(tmem), "r"(ncols));
}
__device__ __forceinline__ void mma_tf32(uint32_t d, uint64_t ad, uint64_t bd,
                                         uint32_t idesc, bool accum) {
  uint32_t en = accum ? 1u : 0u;
  asm volatile(
      "{\n\t.reg .pred p;\n\t"
      "setp.ne.u32 p, %4, 0;\n\t"
      "tcgen05.mma.cta_group::1.kind::tf32 [%0], %1, %2, %3, {%5,%5,%5,%5}, p;\n\t}"
      :: "r"(d), "l"(ad), "l"(bd), "r"(idesc), "r"(en), "r"(0u) : "memory");
}
__device__ __forceinline__ void mma_commit(uint32_t mbar) {
  asm volatile(
      "tcgen05.commit.cta_group::1.mbarrier::arrive::one.shared::cluster.b64 [%0];"
      :: "r"(mbar) : "memory");
}
__device__ __forceinline__ void ldtm_x32(uint32_t* r, uint32_t addr) {
  asm volatile(
      "tcgen05.ld.sync.aligned.32x32b.x32.b32 "
      "{%0,%1,%2,%3,%4,%5,%6,%7,%8,%9,%10,%11,%12,%13,%14,%15,"
      "%16,%17,%18,%19,%20,%21,%22,%23,%24,%25,%26,%27,%28,%29,%30,%31}, [%32];"
      : "=r"(r[0]), "=r"(r[1]), "=r"(r[2]), "=r"(r[3]), "=r"(r[4]), "=r"(r[5]),
        "=r"(r[6]), "=r"(r[7]), "=r"(r[8]), "=r"(r[9]), "=r"(r[10]),
        "=r"(r[11]), "=r"(r[12]), "=r"(r[13]), "=r"(r[14]), "=r"(r[15]),
        "=r"(r[16]), "=r"(r[17]), "=r"(r[18]), "=r"(r[19]), "=r"(r[20]),
        "=r"(r[21]), "=r"(r[22]), "=r"(r[23]), "=r"(r[24]), "=r"(r[25]),
        "=r"(r[26]), "=r"(r[27]), "=r"(r[28]), "=r"(r[29]), "=r"(r[30]),
        "=r"(r[31])
      : "r"(addr));
}
__device__ __forceinline__ void cp16(uint32_t dst, const void* src) {
  asm volatile("cp.async.cg.shared.global [%0], [%1], 16;"
               :: "r"(dst), "l"(src) : "memory");
}
#endif  // USE_TCGEN05

#define SWZ(o) ((o) ^ (((o) >> 3) & 0x70))

// ---------------------------------------------------------------------------
// Uniform NT GEMM: C[M,N] = A[M,K] B[N,K]^T, CTA tile 128x256, 2 CTAs/SM.
// MODE 2: skip 2bn>bm; epilogue mask(c>=row)->0 else *scale, tf32-rounded.
// MODE 3: Keff=(bm+1)*128, raw store, reversed bm.
// MODE 4: fused projections; z=0:(A,B,C) q, z=1:(Ay,Bk,Ck) k,
//         z=2:(Ay,Bv,Cv) transposed store (stride M), all tf32-rounded.
// ---------------------------------------------------------------------------
template <int MODE>
__global__ void __launch_bounds__(256, 2)
tc_k(const float* A, const float* B, float* C,
     const float* Ay, const float* Bk, float* Ck,
     const float* Bv, float* Cv,
     int M, int N, int K, float scale) {
  int tmode = MODE;
  if (MODE == 4) {
    const int z = blockIdx.z;
    if (z == 0)      { tmode = 0; }
    else if (z == 1) { A = Ay; B = Bk; C = Ck; tmode = 0; }
    else             { A = Ay; B = Bv; C = Cv; tmode = 1; }
  }
  int bm = blockIdx.y;
  const int bn = blockIdx.x;
  if (MODE == 3) bm = gridDim.y - 1 - bm;
  if (MODE == 2 && 2 * bn > bm) return;

  const int row0 = bm * BMC, col0 = bn * BNC;
  const int Keff = (MODE == 3) ? min(K, (bm + 1) * BMC) : K;
  const int nT = Keff / KT;
  extern __shared__ char smem[];
  const int tid = threadIdx.x;

#if USE_TCGEN05
  const uint32_t sb = smem_u32(smem);
  if (tid < 32) { tmem_alloc(sb, BNC); tmem_relinq(); }
  if (tid == 0)
    for (int s = 0; s < SS; ++s) mbar_init(sb + MBAR_OFF + 8 * s, 1);
  __syncthreads();
  uint32_t tmem;
  asm volatile("ld.shared.b32 %0, [%1];" : "=r"(tmem) : "r"(sb));

  const int r0  = tid >> 3;          // 0..31
  const int c16 = tid & 7;
  const float* Ag = A + (size_t)(row0 + r0) * K + c16 * 4;
  const float* Bg = B + (size_t)(col0 + r0) * K + c16 * 4;
  const size_t rstep = (size_t)32 * K;
  const int swb = SWZ(r0 * 128 + c16 * 16);

  // prologue: tile 0 -> stage 0
  {
    const uint32_t da = sb + DATA_OFF + swb;
#pragma unroll
    for (int i = 0; i < 4; ++i) cp16(da + i * 4096, Ag + i * rstep);
#pragma unroll
    for (int i = 0; i < 8; ++i) cp16(da + ABYTES + i * 4096, Bg + i * rstep);
  }
  asm volatile("cp.async.commit_group;" ::: "memory");

  for (int t = 0; t < nT; ++t) {
    const int u = t + 1;
    if (u < nT) {
      const int su = u & 1;
      if (u >= SS)  // stage reuse: MMA of tile u-2 must be done
        mbar_wait(sb + MBAR_OFF + 8 * su, ((u - SS) / SS) & 1);
      const uint32_t da = sb + DATA_OFF + su * STB + swb;
      const float* ag = Ag + (size_t)u * KT;
      const float* bg = Bg + (size_t)u * KT;
#pragma unroll
      for (int i = 0; i < 4; ++i) cp16(da + i * 4096, ag + i * rstep);
#pragma unroll
      for (int i = 0; i < 8; ++i) cp16(da + ABYTES + i * 4096, bg + i * rstep);
    }
    asm volatile("cp.async.commit_group;" ::: "memory");
    asm volatile("cp.async.wait_group 1;" ::: "memory");   // tile t arrived
    asm volatile("fence.proxy.async.shared::cta;" ::: "memory");
    __syncthreads();

    if (tid == 0) {
      const int s = t & 1;
      const uint32_t base = sb + DATA_OFF + s * STB;
      const uint64_t ad = DESC_BASE | ((base >> 4) & 0x3FFF);
      const uint64_t bd = DESC_BASE | (((base + ABYTES) >> 4) & 0x3FFF);
#pragma unroll
      for (int ks = 0; ks < 4; ++ks)
        mma_tf32(tmem, ad + 2 * ks, bd + 2 * ks, IDESC, (t > 0) || (ks > 0));
      mma_commit(sb + MBAR_OFF + 8 * s);
    }
  }

  mbar_wait(sb + MBAR_OFF + 8 * ((nT - 1) & 1), ((nT - 1) / SS) & 1);
  asm volatile("tcgen05.fence::after_thread_sync;" ::: "memory");

  const int wg = tid >> 7, sp = (tid >> 5) & 3, lane = tid & 31;
  const int row = row0 + sp * 32 + lane;
  uint32_t r[32];
#pragma unroll
  for (int ch = 0; ch < 4; ++ch) {
    const int colb = wg * 128 + ch * 32;
    ldtm_x32(r, tmem + colb);
    asm volatile("tcgen05.wait::ld.sync.aligned;" ::: "memory");
    asm volatile("tcgen05.fence::before_thread_sync;" ::: "memory");
    if (tmode == 1) {           // transposed, tf32-rounded
#pragma unroll
      for (int j = 0; j < 32; ++j)
        C[(size_t)(col0 + colb + j) * M + row] = tf32r(__uint_as_float(r[j]));
    } else if (tmode == 2) {    // mask + scale, tf32-rounded
      float* cp = C + (size_t)row * N + col0 + colb;
#pragma unroll
      for (int j = 0; j < 32; ++j) {
        const int c = col0 + colb + j;
        cp[j] = (c >= row) ? 0.0f : tf32r(__uint_as_float(r[j]) * scale);
      }
    } else if (tmode == 0) {    // tf32-rounded
      float* cp = C + (size_t)row * N + col0 + colb;
#pragma unroll
      for (int j = 0; j < 32; ++j) cp[j] = tf32r(__uint_as_float(r[j]));
    } else {                    // raw (final out)
      float* cp = C + (size_t)row * N + col0 + colb;
#pragma unroll
      for (int j = 0; j < 32; ++j) cp[j] = __uint_as_float(r[j]);
    }
  }

  __syncthreads();
  if (tid == 0)
    for (int s = 0; s < SS; ++s) mbar_inval(sb + MBAR_OFF + 8 * s);
  if (tid < 32) tmem_dealloc(tmem, BNC);

#elif defined(__CUDA_ARCH__)
  (void)smem; (void)nT;
  for (int e = tid; e < BMC * BNC; e += blockDim.x) {
    const int rr = row0 + e / BNC;
    const int cc = col0 + e % BNC;
    float s = 0.f;
    for (int kk = 0; kk < Keff; ++kk)
      s += A[(size_t)rr * K + kk] * B[(size_t)cc * K + kk];
    if (tmode == 2) s = (cc >= rr) ? 0.f : s * scale;
    if (tmode == 1) C[(size_t)cc * M + rr] = s;
    else            C[(size_t)rr * N + cc] = s;
  }
#endif
}

// ---------------------------------------------------------------------------

extern "C" void kernel_launch(void* const* d_in, const int* in_sizes, int n_in,
                              void* d_out, int out_size) {
  (void)in_sizes; (void)n_in; (void)out_size;
  const float* x  = (const float*)d_in[0];
  const float* y  = (const float*)d_in[1];
  const float* Wq = (const float*)d_in[2];
  const float* Wk = (const float*)d_in[3];
  const float* Wv = (const float*)d_in[4];
  float* out = (float*)d_out;

  float *xc, *yc, *wqc, *wkc, *wvc, *q, *k, *vT, *a;
  cudaGetSymbolAddress((void**)&xc, g_xc);
  cudaGetSymbolAddress((void**)&yc, g_yc);
  cudaGetSymbolAddress((void**)&wqc, g_wqc);
  cudaGetSymbolAddress((void**)&wkc, g_wkc);
  cudaGetSymbolAddress((void**)&wvc, g_wvc);
  cudaGetSymbolAddress((void**)&q, g_q);
  cudaGetSymbolAddress((void**)&k, g_k);
  cudaGetSymbolAddress((void**)&vT, g_vT);
  cudaGetSymbolAddress((void**)&a, g_a);

  cudaFuncSetAttribute(tc_k<2>, cudaFuncAttributeMaxDynamicSharedMemorySize,
                       SMEM_SZ);
  cudaFuncSetAttribute(tc_k<3>, cudaFuncAttributeMaxDynamicSharedMemorySize,
                       SMEM_SZ);
  cudaFuncSetAttribute(tc_k<4>, cudaFuncAttributeMaxDynamicSharedMemorySize,
                       SMEM_SZ);

  dim3 blk(256, 1, 1);
  const float scale = 1.0f / sqrtf((float)kD);

  // Stage 0: RNE-convert weights (one z=3 launch) and x,y (z=2 launch)
  cvt_kernel<<<dim3(64, 1, 3), blk>>>(Wq, wqc, Wk, wkc, Wv, wvc, kD * kC);
  cvt_kernel<<<dim3(1024, 1, 2), blk>>>(x, xc, y, yc, nullptr, nullptr,
                                        kNX * kC);

  // Stage 1: fused projections q,k,vT (128x256, grid 2x64x3)
  tc_k<4><<<dim3(kD / BNC, kNX / BMC, 3), blk, SMEM_SZ>>>(
      xc, wqc, q, yc, wkc, k, wvc, vT, kNX, kD, kC, 1.0f);

  // Stage 2: a = mask(q k^T)*scale (skip 2bn>bm)
  tc_k<2><<<dim3(kNY / BNC, kNX / BMC), blk, SMEM_SZ>>>(
      q, k, a, nullptr, nullptr, nullptr, nullptr, nullptr,
      kNX, kNY, kD, scale);

  // Stage 3: out = a vT^T (K-limited per 128-row block)
  tc_k<3><<<dim3(kD / BNC, kNX / BMC), blk, SMEM_SZ>>>(
      a, vT, out, nullptr, nullptr, nullptr, nullptr, nullptr,
      kNX, kD, kNY, 1.0f);
}

// round 9
// speedup vs baseline: 1.0206x; 1.0206x over previous
#include <cuda_runtime.h>
#include <cstdint>
#include <cmath>

// ---------------------------------------------------------------------------
// Head_55671366091048 (sm_103a), warp-specialized tcgen05 pipeline.
//   Wc = rna(W)
//   q = rna(x) Wqc^T ; k = rna(y) Wkc^T ; vT = (rna(y) Wvc^T)^T  (fused z=3)
//   a = mask(q k^T) * d^-1/2    (strict lower; 128x256 blocks, skip 2bn>bm)
//   out = a vT^T                (per-128-row K limit, reversed bm)
//
// 9 warps/CTA: warps 0-7 produce (cp.async, arrive-on-complete via
// cp.async.mbarrier.arrive.noinc), warp 8 issues MMAs. NO __syncthreads /
// fence / wait_group in the mainloop — rounds 5-8 showed the CTA-wide
// per-tile lockstep costs ~5-7K cyc/tile regardless of tiling/occupancy.
// 128x256 tiles, TMEM 256 cols, S=2 stages, 2 CTAs/SM.
// compute_103 PTX pass gets a naive fallback (never runs on HW).
// ---------------------------------------------------------------------------

#if defined(__CUDA_ARCH__) && defined(__CUDA_ARCH_FEAT_SM103_ALL)
#define USE_TCGEN05 1
#else
#define USE_TCGEN05 0
#endif

namespace {
constexpr int kNX = 8192;
constexpr int kNY = 8192;
constexpr int kC  = 2048;
constexpr int kD  = 512;

constexpr int BMC = 128;
constexpr int BNC = 256;
constexpr int KT  = 32;                  // K per smem tile (128B rows)
constexpr int SS  = 2;                   // stages
constexpr int ABYTES = BMC * 128;        // 16 KB
constexpr int BBYTES = BNC * 128;        // 32 KB
constexpr int STB = ABYTES + BBYTES;     // 48 KB
constexpr int MBAR_OFF = 64;             // full[s] @ +16s, done[s] @ +16s+8
constexpr int DATA_OFF = 1024;
constexpr int SMEM_SZ = DATA_OFF + SS * STB;   // 99328 -> 2 CTAs/SM

constexpr int NTHREADS = 288;            // 8 producer warps + 1 MMA warp

constexpr uint64_t DESC_BASE =
    (uint64_t(2) << 61) | (uint64_t(1) << 46) | (uint64_t(64) << 32) |
    (uint64_t(1) << 16);

// idesc kind::tf32: dtype F32, a/b TF32, N=256, M=128
constexpr uint32_t IDESC =
    (1u << 4) | (2u << 7) | (2u << 10) | ((BNC / 8) << 17) | (8u << 24);
}  // namespace

__device__ float g_wqc[(size_t)kD * kC];
__device__ float g_wkc[(size_t)kD * kC];
__device__ float g_wvc[(size_t)kD * kC];
__device__ float g_q[(size_t)kNX * kD];
__device__ float g_k[(size_t)kNY * kD];
__device__ float g_vT[(size_t)kD * kNY];
__device__ float g_a[(size_t)kNX * kNY];

// ---------------------------------------------------------------------------
__device__ __forceinline__ uint32_t smem_u32(const void* p) {
  uint32_t a;
  asm("{ .reg .u64 t; cvta.to.shared.u64 t, %1; cvt.u32.u64 %0, t; }"
      : "=r"(a) : "l"(p));
  return a;
}
__device__ __forceinline__ float tf32r(float f) {
  uint32_t u;
  asm("cvt.rna.tf32.f32 %0, %1;" : "=r"(u) : "f"(f));
  return __uint_as_float(u);
}
__device__ __forceinline__ float4 tf32r4(float4 v) {
  return make_float4(tf32r(v.x), tf32r(v.y), tf32r(v.z), tf32r(v.w));
}

__global__ void cvt_kernel(const float* s0, float* d0, const float* s1,
                           float* d1, const float* s2, float* d2, int n) {
  const int z = blockIdx.z;
  const float* s = (z == 0) ? s0 : (z == 1) ? s1 : s2;
  float* d = (z == 0) ? d0 : (z == 1) ? d1 : d2;
  int i = (blockIdx.x * blockDim.x + threadIdx.x) * 4;
  const int stride = gridDim.x * blockDim.x * 4;
  for (; i < n; i += stride) *(float4*)(d + i) = tf32r4(*(const float4*)(s + i));
}

#if USE_TCGEN05
__device__ __forceinline__ void mbar_init(uint32_t addr, uint32_t cnt) {
  asm volatile("mbarrier.init.shared.b64 [%0], %1;" :: "r"(addr), "r"(cnt)
               : "memory");
}
__device__ __forceinline__ void mbar_inval(uint32_t addr) {
  asm volatile("mbarrier.inval.shared.b64 [%0];" :: "r"(addr) : "memory");
}
__device__ __forceinline__ void mbar_arrive(uint32_t addr) {
  asm volatile("mbarrier.arrive.shared.b64 _, [%0];" :: "r"(addr) : "memory");
}
__device__ __forceinline__ void mbar_wait(uint32_t addr, uint32_t parity) {
  uint32_t done;
  asm volatile(
      "{\n\t.reg .pred p;\n\t"
      "mbarrier.try_wait.parity.acquire.cta.shared::cta.b64 p, [%1], %2;\n\t"
      "selp.b32 %0, 1, 0, p;\n\t}"
      : "=r"(done) : "r"(addr), "r"(parity) : "memory");
  if (!done) {
    asm volatile(
        "{\n\t.reg .pred P1;\n\t"
        "WL_%=:\n\t"
        "mbarrier.try_wait.parity.acquire.cta.shared::cta.b64 P1, [%0], %1, 0x989680;\n\t"
        "@P1 bra.uni WD_%=;\n\t"
        "bra.uni WL_%=;\n\t"
        "WD_%=:\n\t}"
        :: "r"(addr), "r"(parity) : "memory");
  }
}
__device__ __forceinline__ void tmem_alloc(uint32_t smem_dst, uint32_t ncols) {
  asm volatile(
      "tcgen05.alloc.cta_group::1.sync.aligned.shared::cta.b32 [%0], %1;"
      :: "r"(smem_dst), "r"(ncols) : "memory");
}
__device__ __forceinline__ void tmem_relinq() {
  asm volatile("tcgen05.relinquish_alloc_permit.cta_group::1.sync.aligned;");
}
__device__ __forceinline__ void tmem_dealloc(uint32_t tmem, uint32_t ncols) {
  asm volatile("tcgen05.dealloc.cta_group::1.sync.aligned.b32 %0, %1;"
               :: "r"(tmem), "r"(ncols));
}
__device__ __forceinline__ void mma_tf32(uint32_t d, uint64_t ad, uint64_t bd,
                                         uint32_t idesc, bool accum) {
  uint32_t en = accum ? 1u : 0u;
  asm volatile(
      "{\n\t.reg .pred p;\n\t"
      "setp.ne.u32 p, %4, 0;\n\t"
      "tcgen05.mma.cta_group::1.kind::tf32 [%0], %1, %2, %3, {%5,%5,%5,%5}, p;\n\t}"
      :: "r"(d), "l"(ad), "l"(bd), "r"(idesc), "r"(en), "r"(0u) : "memory");
}
__device__ __forceinline__ void mma_commit(uint32_t mbar) {
  asm volatile(
      "tcgen05.commit.cta_group::1.mbarrier::arrive::one.shared::cluster.b64 [%0];"
      :: "r"(mbar) : "memory");
}
__device__ __forceinline__ void ldtm_x32(uint32_t* r, uint32_t addr) {
  asm volatile(
      "tcgen05.ld.sync.aligned.32x32b.x32.b32 "
      "{%0,%1,%2,%3,%4,%5,%6,%7,%8,%9,%10,%11,%12,%13,%14,%15,"
      "%16,%17,%18,%19,%20,%21,%22,%23,%24,%25,%26,%27,%28,%29,%30,%31}, [%32];"
      : "=r"(r[0]), "=r"(r[1]), "=r"(r[2]), "=r"(r[3]), "=r"(r[4]), "=r"(r[5]),
        "=r"(r[6]), "=r"(r[7]), "=r"(r[8]), "=r"(r[9]), "=r"(r[10]),
        "=r"(r[11]), "=r"(r[12]), "=r"(r[13]), "=r"(r[14]), "=r"(r[15]),
        "=r"(r[16]), "=r"(r[17]), "=r"(r[18]), "=r"(r[19]), "=r"(r[20]),
        "=r"(r[21]), "=r"(r[22]), "=r"(r[23]), "=r"(r[24]), "=r"(r[25]),
        "=r"(r[26]), "=r"(r[27]), "=r"(r[28]), "=r"(r[29]), "=r"(r[30]),
        "=r"(r[31])
      : "r"(addr));
}
__device__ __forceinline__ void cp16(uint32_t dst, const void* src) {
  asm volatile("cp.async.cg.shared.global [%0], [%1], 16;"
               :: "r"(dst), "l"(src) : "memory");
}
__device__ __forceinline__ void cp_arrive_noinc(uint32_t mbar) {
  asm volatile("cp.async.mbarrier.arrive.noinc.shared.b64 [%0];"
               :: "r"(mbar) : "memory");
}
#endif  // USE_TCGEN05

#define SWZ(o) ((o) ^ (((o) >> 3) & 0x70))

// ---------------------------------------------------------------------------
// Warp-specialized NT GEMM: C[M,N] = A[M,K] B[N,K]^T, 128x256 CTA tile.
// MODE 2: skip 2bn>bm; mask+scale epilogue (tf32-rounded).
// MODE 3: Keff=(bm+1)*128, raw store, reversed bm.
// MODE 4: fused projections; A converted in-producer (LDG->rna->STS);
//         z=0 -> q, z=1 -> k, z=2 -> vT (transposed store), tf32-rounded.
// ---------------------------------------------------------------------------
template <int MODE>
__global__ void __launch_bounds__(NTHREADS, 2)
tc_ws(const float* A, const float* B, float* C,
      const float* Ay, const float* Bk, float* Ck,
      const float* Bv, float* Cv,
      int M, int N, int K, float scale) {
  int tmode = MODE;
  if (MODE == 4) {
    const int z = blockIdx.z;
    if (z == 0)      { tmode = 0; }
    else if (z == 1) { A = Ay; B = Bk; C = Ck; tmode = 0; }
    else             { A = Ay; B = Bv; C = Cv; tmode = 1; }
  }
  int bm = blockIdx.y;
  const int bn = blockIdx.x;
  if (MODE == 3) bm = gridDim.y - 1 - bm;
  if (MODE == 2 && 2 * bn > bm) return;

  const int row0 = bm * BMC, col0 = bn * BNC;
  const int Keff = (MODE == 3) ? min(K, (bm + 1) * BMC) : K;
  const int nT = Keff / KT;
  extern __shared__ char smem[];
  const int tid = threadIdx.x;
  const int wid = tid >> 5;

#if USE_TCGEN05
  const uint32_t sb = smem_u32(smem);
  constexpr uint32_t FULL_CNT = (MODE == 4) ? 512u : 256u;

  if (wid == 8) { tmem_alloc(sb, BNC); tmem_relinq(); }
  if (tid == 0) {
#pragma unroll
    for (int s = 0; s < SS; ++s) {
      mbar_init(sb + MBAR_OFF + 16 * s, FULL_CNT);      // full[s]
      mbar_init(sb + MBAR_OFF + 16 * s + 8, 1);         // done[s]
    }
  }
  __syncthreads();
  uint32_t tmem;
  asm volatile("ld.shared.b32 %0, [%1];" : "=r"(tmem) : "r"(sb));

  if (tid < 256) {
    // ---------------- producers (warps 0-7) ----------------
    // B mapping: 8 x 16B per thread
    const int r0  = tid >> 3;
    const int c16 = tid & 7;
    const float* Bg = B + (size_t)(col0 + r0) * K + c16 * 4;
    const size_t rstep = (size_t)32 * K;
    const int swB = SWZ(r0 * 128 + c16 * 16);
    // A mapping (MODE 2/3: cp.async 4x16B;  MODE 4: LDG+cvt+STS 4x16B)
    const int ar = (MODE == 4) ? (tid >> 1) : r0;        // row within tile
    const int ac = (MODE == 4) ? ((tid & 1) * 16) : (c16 * 4);
    const float* Ag = A + (size_t)(row0 + ar) * K + ac;
    const int swA = (MODE == 4) ? 0 : SWZ(r0 * 128 + c16 * 16);

    for (int t = 0; t < nT; ++t) {
      const int s = t & 1;
      if (t >= SS) mbar_wait(sb + MBAR_OFF + 16 * s + 8, ((t >> 1) - 1) & 1);
      const uint32_t base = sb + DATA_OFF + s * STB;

      if (MODE == 4) {
        // A: LDG -> rna -> STS (covered by release-arrive below)
        const float* ap = Ag + (size_t)t * KT;
        float4 v0 = *(const float4*)(ap + 0);
        float4 v1 = *(const float4*)(ap + 4);
        float4 v2 = *(const float4*)(ap + 8);
        float4 v3 = *(const float4*)(ap + 12);
        char* d = smem + DATA_OFF + s * STB;
        const int bo = ar * 128 + (tid & 1) * 64;
        *(float4*)(d + SWZ(bo + 0))  = tf32r4(v0);
        *(float4*)(d + SWZ(bo + 16)) = tf32r4(v1);
        *(float4*)(d + SWZ(bo + 32)) = tf32r4(v2);
        *(float4*)(d + SWZ(bo + 48)) = tf32r4(v3);
      } else {
        const float* ap = Ag + (size_t)t * KT;
#pragma unroll
        for (int i = 0; i < 4; ++i)
          cp16(base + swA + i * 4096, ap + i * rstep);
      }
      // B: cp.async 8 chunks
      {
        const float* bp = Bg + (size_t)t * KT;
#pragma unroll
        for (int i = 0; i < 8; ++i)
          cp16(base + ABYTES + swB + i * 4096, bp + i * rstep);
      }
      if (MODE == 4) mbar_arrive(sb + MBAR_OFF + 16 * s);   // release STS
      cp_arrive_noinc(sb + MBAR_OFF + 16 * s);              // cp completion
    }

    // ---------------- epilogue (warps 0-7) ----------------
    mbar_wait(sb + MBAR_OFF + 16 * ((nT - 1) & 1) + 8, ((nT - 1) >> 1) & 1);
    asm volatile("tcgen05.fence::after_thread_sync;" ::: "memory");

    const int wg = tid >> 7, sp = (tid >> 5) & 3, lane = tid & 31;
    const int row = row0 + sp * 32 + lane;
    uint32_t r[32];
#pragma unroll
    for (int ch = 0; ch < 4; ++ch) {
      const int colb = wg * 128 + ch * 32;
      ldtm_x32(r, tmem + colb);
      asm volatile("tcgen05.wait::ld.sync.aligned;" ::: "memory");
      if (tmode == 1) {
#pragma unroll
        for (int j = 0; j < 32; ++j)
          C[(size_t)(col0 + colb + j) * M + row] = tf32r(__uint_as_float(r[j]));
      } else if (tmode == 2) {
        float* cp = C + (size_t)row * N + col0 + colb;
#pragma unroll
        for (int j = 0; j < 32; ++j) {
          const int c = col0 + colb + j;
          cp[j] = (c >= row) ? 0.0f : tf32r(__uint_as_float(r[j]) * scale);
        }
      } else if (tmode == 0) {
        float* cp = C + (size_t)row * N + col0 + colb;
#pragma unroll
        for (int j = 0; j < 32; ++j) cp[j] = tf32r(__uint_as_float(r[j]));
      } else {
        float* cp = C + (size_t)row * N + col0 + colb;
#pragma unroll
        for (int j = 0; j < 32; ++j) cp[j] = __uint_as_float(r[j]);
      }
    }
  } else {
    // ---------------- MMA warp (warp 8) ----------------
    const int lane = tid & 31;
    for (int t = 0; t < nT; ++t) {
      const int s = t & 1;
      mbar_wait(sb + MBAR_OFF + 16 * s, (t >> 1) & 1);
      if (lane == 0) {
        asm volatile("fence.proxy.async.shared::cta;" ::: "memory");
        const uint32_t base = sb + DATA_OFF + s * STB;
        const uint64_t ad = DESC_BASE | ((base >> 4) & 0x3FFF);
        const uint64_t bd = DESC_BASE | (((base + ABYTES) >> 4) & 0x3FFF);
#pragma unroll
        for (int ks = 0; ks < 4; ++ks)
          mma_tf32(tmem, ad + 2 * ks, bd + 2 * ks, IDESC, (t > 0) || (ks > 0));
        mma_commit(sb + MBAR_OFF + 16 * s + 8);
      }
      __syncwarp();
    }
  }

  __syncthreads();   // epilogue done everywhere before teardown
  if (tid == 0) {
#pragma unroll
    for (int s = 0; s < SS; ++s) {
      mbar_inval(sb + MBAR_OFF + 16 * s);
      mbar_inval(sb + MBAR_OFF + 16 * s + 8);
    }
  }
  if (wid == 8) tmem_dealloc(tmem, BNC);

#elif defined(__CUDA_ARCH__)
  (void)smem; (void)nT; (void)wid;
  for (int e = tid; e < BMC * BNC; e += blockDim.x) {
    const int rr = row0 + e / BNC;
    const int cc = col0 + e % BNC;
    float s = 0.f;
    for (int kk = 0; kk < Keff; ++kk)
      s += A[(size_t)rr * K + kk] * B[(size_t)cc * K + kk];
    if (tmode == 2) s = (cc >= rr) ? 0.f : s * scale;
    if (tmode == 1) C[(size_t)cc * M + rr] = s;
    else            C[(size_t)rr * N + cc] = s;
  }
#endif
}

// ---------------------------------------------------------------------------

extern "C" void kernel_launch(void* const* d_in, const int* in_sizes, int n_in,
                              void* d_out, int out_size) {
  (void)in_sizes; (void)n_in; (void)out_size;
  const float* x  = (const float*)d_in[0];
  const float* y  = (const float*)d_in[1];
  const float* Wq = (const float*)d_in[2];
  const float* Wk = (const float*)d_in[3];
  const float* Wv = (const float*)d_in[4];
  float* out = (float*)d_out;

  float *wqc, *wkc, *wvc, *q, *k, *vT, *a;
  cudaGetSymbolAddress((void**)&wqc, g_wqc);
  cudaGetSymbolAddress((void**)&wkc, g_wkc);
  cudaGetSymbolAddress((void**)&wvc, g_wvc);
  cudaGetSymbolAddress((void**)&q, g_q);
  cudaGetSymbolAddress((void**)&k, g_k);
  cudaGetSymbolAddress((void**)&vT, g_vT);
  cudaGetSymbolAddress((void**)&a, g_a);

  cudaFuncSetAttribute(tc_ws<2>, cudaFuncAttributeMaxDynamicSharedMemorySize,
                       SMEM_SZ);
  cudaFuncSetAttribute(tc_ws<3>, cudaFuncAttributeMaxDynamicSharedMemorySize,
                       SMEM_SZ);
  cudaFuncSetAttribute(tc_ws<4>, cudaFuncAttributeMaxDynamicSharedMemorySize,
                       SMEM_SZ);

  dim3 blk(NTHREADS, 1, 1);
  const float scale = 1.0f / sqrtf((float)kD);

  // Stage 0: RNE-convert weights only (12 MB)
  cvt_kernel<<<dim3(64, 1, 3), dim3(256, 1, 1)>>>(Wq, wqc, Wk, wkc, Wv, wvc,
                                                  kD * kC);

  // Stage 1: fused projections q, k, vT (x/y converted in-producer)
  tc_ws<4><<<dim3(kD / BNC, kNX / BMC, 3), blk, SMEM_SZ>>>(
      x, wqc, q, y, wkc, k, wvc, vT, kNX, kD, kC, 1.0f);

  // Stage 2: a = mask(q k^T)*scale (skip 2bn>bm)
  tc_ws<2><<<dim3(kNY / BNC, kNX / BMC), blk, SMEM_SZ>>>(
      q, k, a, nullptr, nullptr, nullptr, nullptr, nullptr,
      kNX, kNY, kD, scale);

  // Stage 3: out = a vT^T (K-limited per 128-row block, reversed bm)
  tc_ws<3><<<dim3(kD / BNC, kNX / BMC), blk, SMEM_SZ>>>(
      a, vT, out, nullptr, nullptr, nullptr, nullptr, nullptr,
      kNX, kD, kNY, 1.0f);
}